// round 1
// baseline (speedup 1.0000x reference)
#include <cuda_runtime.h>
#include <math.h>

#define BATCH  8
#define SEQ    2048
#define MTOT   (BATCH*SEQ)      // 16384
#define DIN    64
#define HID    256
#define DMODEL 512
#define DINNER 1024
#define DSTATE 16
#define DTRANK 32
#define DCONV  4
#define DOUTD  64

// ---------------- scratch (allocation-free, __device__ globals) ----------------
__device__ float g_h    [MTOT*HID];        // encoder hidden
__device__ float g_u    [MTOT*DMODEL];     // encoder out
__device__ float g_xz   [MTOT*2*DINNER];   // in_proj out (xm | z)
__device__ float g_xm   [MTOT*DINNER];     // conv+silu out
__device__ float g_dbl  [MTOT*64];         // x_proj out [dt(32)|B(16)|C(16)]
__device__ float g_delta[MTOT*DINNER];     // softplus(dt_proj)
__device__ float g_y    [MTOT*DINNER];     // scan out (then gated in-place)
__device__ float g_o1   [MTOT*DMODEL];     // out_proj out
__device__ float g_h2   [MTOT*HID];        // decoder hidden

enum Act { ACT_NONE = 0, ACT_RELU = 1, ACT_SOFTPLUS = 2 };

// ---------------- tiled fp32 SGEMM:  C[M,N] = act(A[M,K(lda)] * W[N,K]^T + bias) ----------------
template<int BM, int BN, int BK, int TM, int TN, int ACT>
__global__ void __launch_bounds__((BM/TM)*(BN/TN))
gemm_nt(const float* __restrict__ A, const float* __restrict__ W,
        const float* __restrict__ bias, float* __restrict__ C,
        int M, int N, int K, int lda)
{
    constexpr int THREADS = (BM/TM)*(BN/TN);
    __shared__ float As[BK][BM + 4];
    __shared__ float Ws[BK][BN + 4];

    const int tid = threadIdx.x;
    const int tn  = tid % (BN/TN);
    const int tm  = tid / (BN/TN);
    const int bm  = blockIdx.y * BM;
    const int bn  = blockIdx.x * BN;

    float acc[TM][TN];
#pragma unroll
    for (int i = 0; i < TM; i++)
#pragma unroll
        for (int j = 0; j < TN; j++) acc[i][j] = 0.f;

    for (int k0 = 0; k0 < K; k0 += BK) {
        // A tile (BM x BK), stored transposed As[k][m]
        for (int i = tid; i < BM*(BK/4); i += THREADS) {
            int m  = i / (BK/4);
            int kk = (i % (BK/4)) * 4;
            float4 v = *(const float4*)(A + (size_t)(bm + m)*lda + (k0 + kk));
            As[kk+0][m] = v.x; As[kk+1][m] = v.y; As[kk+2][m] = v.z; As[kk+3][m] = v.w;
        }
        // W tile (BN x BK), stored transposed Ws[k][n]
        for (int i = tid; i < BN*(BK/4); i += THREADS) {
            int n  = i / (BK/4);
            int kk = (i % (BK/4)) * 4;
            float4 v = *(const float4*)(W + (size_t)(bn + n)*K + (k0 + kk));
            Ws[kk+0][n] = v.x; Ws[kk+1][n] = v.y; Ws[kk+2][n] = v.z; Ws[kk+3][n] = v.w;
        }
        __syncthreads();

#pragma unroll
        for (int kk = 0; kk < BK; kk++) {
            float af[TM], wf[TN];
#pragma unroll
            for (int i = 0; i < TM; i++) af[i] = As[kk][tm*TM + i];
#pragma unroll
            for (int j = 0; j < TN; j++) wf[j] = Ws[kk][tn*TN + j];
#pragma unroll
            for (int i = 0; i < TM; i++)
#pragma unroll
                for (int j = 0; j < TN; j++) acc[i][j] = fmaf(af[i], wf[j], acc[i][j]);
        }
        __syncthreads();
    }

#pragma unroll
    for (int i = 0; i < TM; i++) {
        int m = bm + tm*TM + i;
#pragma unroll
        for (int j = 0; j < TN; j++) {
            int n = bn + tn*TN + j;
            float v = acc[i][j];
            if (bias) v += bias[n];
            if (ACT == ACT_RELU)     v = fmaxf(v, 0.f);
            if (ACT == ACT_SOFTPLUS) v = (v > 20.f) ? v : log1pf(__expf(v));
            C[(size_t)m*N + n] = v;
        }
    }
}

// ---------------- depthwise causal conv1d (k=4) + bias + SiLU ----------------
__global__ void conv_silu_kernel(const float* __restrict__ conv_w,
                                 const float* __restrict__ conv_b)
{
    int idx = blockIdx.x * blockDim.x + threadIdx.x;
    if (idx >= MTOT * DINNER) return;
    int d  = idx % DINNER;
    int bt = idx / DINNER;
    int t  = bt % SEQ;
    int b  = bt / SEQ;

    float acc = conv_b[d];
#pragma unroll
    for (int j = 0; j < DCONV; j++) {
        int tt = t - (DCONV - 1) + j;
        if (tt >= 0)
            acc = fmaf(conv_w[d*DCONV + j],
                       g_xz[(size_t)(b*SEQ + tt)*(2*DINNER) + d], acc);
    }
    float sv = acc / (1.f + __expf(-acc));     // silu
    g_xm[(size_t)bt*DINNER + d] = sv;
}

// ---------------- selective scan: lane-per-(b,d,s), shfl reduce over 16 states ----------------
__global__ void scan_kernel(const float* __restrict__ A_log)
{
    int gid = blockIdx.x * blockDim.x + threadIdx.x;
    int grp = gid >> 4;          // (b,d) index
    int s   = gid & 15;          // state index
    if (grp >= BATCH * DINNER) return;
    int b = grp / DINNER;
    int d = grp % DINNER;

    const float Av = -__expf(A_log[d*DSTATE + s]);
    const float* drow = g_delta + (size_t)b*SEQ*DINNER + d;
    const float* xrow = g_xm    + (size_t)b*SEQ*DINNER + d;
    const float* dblb = g_dbl   + (size_t)b*SEQ*64;
    float*       yrow = g_y     + (size_t)b*SEQ*DINNER + d;

    float h = 0.f;
    for (int t = 0; t < SEQ; t++) {
        float dt = drow[(size_t)t*DINNER];
        float xt = xrow[(size_t)t*DINNER];
        float Bt = dblb[t*64 + DTRANK + s];
        float Ct = dblb[t*64 + DTRANK + DSTATE + s];
        float dA = __expf(dt * Av);
        h = fmaf(dA, h, dt * xt * Bt);
        float p = h * Ct;
        p += __shfl_xor_sync(0xffffffffu, p, 8, 16);
        p += __shfl_xor_sync(0xffffffffu, p, 4, 16);
        p += __shfl_xor_sync(0xffffffffu, p, 2, 16);
        p += __shfl_xor_sync(0xffffffffu, p, 1, 16);
        if (s == 0) yrow[(size_t)t*DINNER] = p;
    }
}

// ---------------- gating: y = (y + xm*D) * silu(z) ----------------
__global__ void gate_kernel(const float* __restrict__ D_param)
{
    int idx = blockIdx.x * blockDim.x + threadIdx.x;
    if (idx >= MTOT * DINNER) return;
    int d  = idx % DINNER;
    int bt = idx / DINNER;
    float z  = g_xz[(size_t)bt*(2*DINNER) + DINNER + d];
    float yv = g_y[idx] + g_xm[idx] * D_param[d];
    g_y[idx] = yv * (z / (1.f + __expf(-z)));
}

// ---------------- host launch ----------------
static float* sym_addr(const void* symbol)
{
    void* p = nullptr;
    cudaGetSymbolAddress(&p, symbol);
    return (float*)p;
}

extern "C" void kernel_launch(void* const* d_in, const int* in_sizes, int n_in,
                              void* d_out, int out_size)
{
    const float* x         = (const float*)d_in[0];
    const float* enc_w1    = (const float*)d_in[1];
    const float* enc_b1    = (const float*)d_in[2];
    const float* enc_w2    = (const float*)d_in[3];
    const float* enc_b2    = (const float*)d_in[4];
    const float* in_proj_w = (const float*)d_in[5];
    const float* conv_w    = (const float*)d_in[6];
    const float* conv_b    = (const float*)d_in[7];
    const float* x_proj_w  = (const float*)d_in[8];
    const float* dt_proj_w = (const float*)d_in[9];
    const float* dt_proj_b = (const float*)d_in[10];
    const float* A_log     = (const float*)d_in[11];
    const float* D_param   = (const float*)d_in[12];
    const float* out_proj_w= (const float*)d_in[13];
    const float* dec_w1    = (const float*)d_in[14];
    const float* dec_b1    = (const float*)d_in[15];
    const float* dec_w2    = (const float*)d_in[16];
    const float* dec_b2    = (const float*)d_in[17];
    float* out = (float*)d_out;

    float* ph    = sym_addr(g_h);
    float* pu    = sym_addr(g_u);
    float* pxz   = sym_addr(g_xz);
    float* pxm   = sym_addr(g_xm);
    float* pdbl  = sym_addr(g_dbl);
    float* pdel  = sym_addr(g_delta);
    float* py    = sym_addr(g_y);
    float* po1   = sym_addr(g_o1);
    float* ph2   = sym_addr(g_h2);
    (void)pxm; (void)py; // kernels referencing globals directly

    const int EW = MTOT * DINNER;
    const int EW_BLK = 256;
    const int EW_GRID = (EW + EW_BLK - 1) / EW_BLK;

    // 1. encoder layer 1: relu(x @ enc_w1^T + b1)   [16384,256] K=64
    gemm_nt<128,128,16,8,8,ACT_RELU><<<dim3(HID/128, MTOT/128), 256>>>(
        x, enc_w1, enc_b1, ph, MTOT, HID, DIN, DIN);

    // 2. encoder layer 2: u = h @ enc_w2^T + b2     [16384,512] K=256
    gemm_nt<128,128,16,8,8,ACT_NONE><<<dim3(DMODEL/128, MTOT/128), 256>>>(
        ph, enc_w2, enc_b2, pu, MTOT, DMODEL, HID, HID);

    // 3. in_proj: xz = u @ in_proj_w^T              [16384,2048] K=512
    gemm_nt<128,128,16,8,8,ACT_NONE><<<dim3(2*DINNER/128, MTOT/128), 256>>>(
        pu, in_proj_w, nullptr, pxz, MTOT, 2*DINNER, DMODEL, DMODEL);

    // 4. depthwise causal conv + bias + silu -> g_xm
    conv_silu_kernel<<<EW_GRID, EW_BLK>>>(conv_w, conv_b);

    // 5. x_proj: dbl = xm @ x_proj_w^T              [16384,64] K=1024
    gemm_nt<128,64,16,8,4,ACT_NONE><<<dim3(64/64, MTOT/128), 256>>>(
        pxm, x_proj_w, nullptr, pdbl, MTOT, 64, DINNER, DINNER);

    // 6. dt_proj + softplus: delta                  [16384,1024] K=32, lda=64
    gemm_nt<128,128,16,8,8,ACT_SOFTPLUS><<<dim3(DINNER/128, MTOT/128), 256>>>(
        pdbl, dt_proj_w, dt_proj_b, pdel, MTOT, DINNER, DTRANK, 64);

    // 7. selective scan -> g_y
    scan_kernel<<<(BATCH*DINNER*DSTATE)/256, 256>>>(A_log);

    // 8. gating: y = (y + xm*D) * silu(z)
    gate_kernel<<<EW_GRID, EW_BLK>>>(D_param);

    // 9. out_proj: o1 = y @ out_proj_w^T            [16384,512] K=1024
    gemm_nt<128,128,16,8,8,ACT_NONE><<<dim3(DMODEL/128, MTOT/128), 256>>>(
        py, out_proj_w, nullptr, po1, MTOT, DMODEL, DINNER, DINNER);

    // 10. decoder layer 1: relu                     [16384,256] K=512
    gemm_nt<128,128,16,8,8,ACT_RELU><<<dim3(HID/128, MTOT/128), 256>>>(
        po1, dec_w1, dec_b1, ph2, MTOT, HID, DMODEL, DMODEL);

    // 11. decoder layer 2 -> out                    [16384,64] K=256
    gemm_nt<128,64,16,8,4,ACT_NONE><<<dim3(DOUTD/64, MTOT/128), 256>>>(
        ph2, dec_w2, dec_b2, out, MTOT, DOUTD, HID, HID);
}

// round 2
// speedup vs baseline: 1.9874x; 1.9874x over previous
#include <cuda_runtime.h>
#include <math.h>
#include <stdint.h>

#define BATCH  8
#define SEQ    2048
#define MTOT   (BATCH*SEQ)      // 16384
#define DIN    64
#define HID    256
#define DMODEL 512
#define DINNER 1024
#define DSTATE 16
#define DTRANK 32
#define DCONV  4
#define DOUTD  64

// ---------------- scratch (allocation-free, __device__ globals) ----------------
__device__ float g_h    [MTOT*HID];        // encoder hidden
__device__ float g_u    [MTOT*DMODEL];     // encoder out
__device__ float g_xz   [MTOT*2*DINNER];   // in_proj out (xm | z)
__device__ float g_xm   [MTOT*DINNER];     // conv+silu out
__device__ float g_dbl  [MTOT*64];         // x_proj out [dt(32)|B(16)|C(16)]
__device__ float g_delta[MTOT*DINNER];     // softplus(dt_proj)
__device__ float g_y    [MTOT*DINNER];     // scan out (then gated in-place)
__device__ float g_o1   [MTOT*DMODEL];     // out_proj out
__device__ float g_h2   [MTOT*HID];        // decoder hidden

enum Act { ACT_NONE = 0, ACT_RELU = 1, ACT_SOFTPLUS = 2 };

// ---------------- tf32 helpers ----------------
__device__ __forceinline__ float to_tf32(float x) {
    float r;
    asm("cvt.rna.tf32.f32 %0, %1;" : "=f"(r) : "f"(x));
    return r;
}

__device__ __forceinline__ void mma8(float c[4], const uint32_t a[4], const uint32_t b[2]) {
    asm volatile(
        "mma.sync.aligned.m16n8k8.row.col.f32.tf32.tf32.f32 "
        "{%0,%1,%2,%3}, {%4,%5,%6,%7}, {%8,%9}, {%0,%1,%2,%3};\n"
        : "+f"(c[0]), "+f"(c[1]), "+f"(c[2]), "+f"(c[3])
        : "r"(a[0]), "r"(a[1]), "r"(a[2]), "r"(a[3]),
          "r"(b[0]), "r"(b[1]));
}

// ---------------- tensor-core GEMM:  C[M,N] = act(A[M,K(lda)] * W[N,K]^T + bias)
// SPLIT=0: plain tf32.  SPLIT=1: tf32x3 (hi/lo split, fp32-class accuracy).
template<int BM,int BN,int WARPS_M,int WARPS_N,int ACT,int SPLIT>
__global__ void __launch_bounds__(WARPS_M*WARPS_N*32)
gemm_tc(const float* __restrict__ A, const float* __restrict__ W,
        const float* __restrict__ bias, float* __restrict__ C,
        int M, int N, int K, int lda)
{
    constexpr int BK = 32, SK = BK + 4;
    constexpr int THREADS = WARPS_M*WARPS_N*32;
    constexpr int WM = BM/WARPS_M, WN = BN/WARPS_N;
    constexpr int MM = WM/16, MN = WN/8;
    constexpr int NBUF = SPLIT ? 2 : 1;

    extern __shared__ float sm[];
    float* sAh = sm;
    float* sAl = sAh + BM*SK;              // only used if SPLIT
    float* sBh = sm + NBUF*BM*SK;
    float* sBl = sBh + BN*SK;              // only used if SPLIT

    const int tid  = threadIdx.x;
    const int lane = tid & 31;
    const int warp = tid >> 5;
    const int g    = lane >> 2;            // groupID 0..7
    const int c4   = lane & 3;             // threadID_in_group 0..3
    const int wrow = (warp / WARPS_N) * WM;
    const int wcol = (warp % WARPS_N) * WN;
    const int bm   = blockIdx.y * BM;
    const int bn   = blockIdx.x * BN;

    float acc[MM][MN][4];
#pragma unroll
    for (int i = 0; i < MM; i++)
#pragma unroll
        for (int j = 0; j < MN; j++)
#pragma unroll
            for (int q = 0; q < 4; q++) acc[i][j][q] = 0.f;

    for (int k0 = 0; k0 < K; k0 += BK) {
        // load + convert A tile (BM x BK)
        for (int i = tid; i < BM*(BK/4); i += THREADS) {
            int m  = i / (BK/4);
            int kc = (i % (BK/4)) * 4;
            float4 v = *(const float4*)(A + (size_t)(bm + m)*lda + k0 + kc);
            float4 h = make_float4(to_tf32(v.x), to_tf32(v.y), to_tf32(v.z), to_tf32(v.w));
            *(float4*)(sAh + m*SK + kc) = h;
            if (SPLIT) {
                float4 l = make_float4(to_tf32(v.x - h.x), to_tf32(v.y - h.y),
                                       to_tf32(v.z - h.z), to_tf32(v.w - h.w));
                *(float4*)(sAl + m*SK + kc) = l;
            }
        }
        // load + convert W tile (BN x BK)
        for (int i = tid; i < BN*(BK/4); i += THREADS) {
            int n  = i / (BK/4);
            int kc = (i % (BK/4)) * 4;
            float4 v = *(const float4*)(W + (size_t)(bn + n)*K + k0 + kc);
            float4 h = make_float4(to_tf32(v.x), to_tf32(v.y), to_tf32(v.z), to_tf32(v.w));
            *(float4*)(sBh + n*SK + kc) = h;
            if (SPLIT) {
                float4 l = make_float4(to_tf32(v.x - h.x), to_tf32(v.y - h.y),
                                       to_tf32(v.z - h.z), to_tf32(v.w - h.w));
                *(float4*)(sBl + n*SK + kc) = l;
            }
        }
        __syncthreads();

#pragma unroll
        for (int kk = 0; kk < BK; kk += 8) {
            uint32_t ah[MM][4], al[MM][4];
#pragma unroll
            for (int mi = 0; mi < MM; mi++) {
                const float* p = sAh + (wrow + mi*16 + g)*SK + kk + c4;
                ah[mi][0] = __float_as_uint(p[0]);
                ah[mi][1] = __float_as_uint(p[8*SK]);
                ah[mi][2] = __float_as_uint(p[4]);
                ah[mi][3] = __float_as_uint(p[8*SK + 4]);
                if (SPLIT) {
                    const float* q = sAl + (wrow + mi*16 + g)*SK + kk + c4;
                    al[mi][0] = __float_as_uint(q[0]);
                    al[mi][1] = __float_as_uint(q[8*SK]);
                    al[mi][2] = __float_as_uint(q[4]);
                    al[mi][3] = __float_as_uint(q[8*SK + 4]);
                }
            }
#pragma unroll
            for (int ni = 0; ni < MN; ni++) {
                const float* p = sBh + (wcol + ni*8 + g)*SK + kk + c4;
                uint32_t bh[2] = { __float_as_uint(p[0]), __float_as_uint(p[4]) };
                uint32_t bl[2];
                if (SPLIT) {
                    const float* q = sBl + (wcol + ni*8 + g)*SK + kk + c4;
                    bl[0] = __float_as_uint(q[0]);
                    bl[1] = __float_as_uint(q[4]);
                }
#pragma unroll
                for (int mi = 0; mi < MM; mi++) {
                    if (SPLIT) {
                        mma8(acc[mi][ni], al[mi], bh);
                        mma8(acc[mi][ni], ah[mi], bl);
                    }
                    mma8(acc[mi][ni], ah[mi], bh);
                }
            }
        }
        __syncthreads();
    }

    // epilogue
#pragma unroll
    for (int mi = 0; mi < MM; mi++) {
        int r0 = bm + wrow + mi*16 + g;
#pragma unroll
        for (int ni = 0; ni < MN; ni++) {
            int col = bn + wcol + ni*8 + 2*c4;
            float b0 = 0.f, b1 = 0.f;
            if (bias) { b0 = bias[col]; b1 = bias[col + 1]; }
            float v0 = acc[mi][ni][0] + b0;
            float v1 = acc[mi][ni][1] + b1;
            float v2 = acc[mi][ni][2] + b0;
            float v3 = acc[mi][ni][3] + b1;
            if (ACT == ACT_RELU) {
                v0 = fmaxf(v0, 0.f); v1 = fmaxf(v1, 0.f);
                v2 = fmaxf(v2, 0.f); v3 = fmaxf(v3, 0.f);
            }
            if (ACT == ACT_SOFTPLUS) {
                v0 = (v0 > 20.f) ? v0 : log1pf(__expf(v0));
                v1 = (v1 > 20.f) ? v1 : log1pf(__expf(v1));
                v2 = (v2 > 20.f) ? v2 : log1pf(__expf(v2));
                v3 = (v3 > 20.f) ? v3 : log1pf(__expf(v3));
            }
            *(float2*)(C + (size_t)r0*N + col)       = make_float2(v0, v1);
            *(float2*)(C + (size_t)(r0 + 8)*N + col) = make_float2(v2, v3);
        }
    }
}

// ---------------- depthwise causal conv1d (k=4) + bias + SiLU ----------------
__global__ void conv_silu_kernel(const float* __restrict__ conv_w,
                                 const float* __restrict__ conv_b)
{
    int idx = blockIdx.x * blockDim.x + threadIdx.x;
    if (idx >= MTOT * DINNER) return;
    int d  = idx % DINNER;
    int bt = idx / DINNER;
    int t  = bt % SEQ;
    int b  = bt / SEQ;

    float acc = conv_b[d];
#pragma unroll
    for (int j = 0; j < DCONV; j++) {
        int tt = t - (DCONV - 1) + j;
        if (tt >= 0)
            acc = fmaf(conv_w[d*DCONV + j],
                       g_xz[(size_t)(b*SEQ + tt)*(2*DINNER) + d], acc);
    }
    float sv = acc / (1.f + __expf(-acc));     // silu
    g_xm[(size_t)bt*DINNER + d] = sv;
}

// ---------------- selective scan: lane-per-(b,d,s), shfl reduce over 16 states ----------------
__global__ void scan_kernel(const float* __restrict__ A_log)
{
    int gid = blockIdx.x * blockDim.x + threadIdx.x;
    int grp = gid >> 4;          // (b,d) index
    int s   = gid & 15;          // state index
    if (grp >= BATCH * DINNER) return;
    int b = grp / DINNER;
    int d = grp % DINNER;

    const float Av = -__expf(A_log[d*DSTATE + s]);
    const float* drow = g_delta + (size_t)b*SEQ*DINNER + d;
    const float* xrow = g_xm    + (size_t)b*SEQ*DINNER + d;
    const float* dblb = g_dbl   + (size_t)b*SEQ*64;
    float*       yrow = g_y     + (size_t)b*SEQ*DINNER + d;

    float h = 0.f;
    for (int t = 0; t < SEQ; t++) {
        float dt = drow[(size_t)t*DINNER];
        float xt = xrow[(size_t)t*DINNER];
        float Bt = dblb[t*64 + DTRANK + s];
        float Ct = dblb[t*64 + DTRANK + DSTATE + s];
        float dA = __expf(dt * Av);
        h = fmaf(dA, h, dt * xt * Bt);
        float p = h * Ct;
        p += __shfl_xor_sync(0xffffffffu, p, 8, 16);
        p += __shfl_xor_sync(0xffffffffu, p, 4, 16);
        p += __shfl_xor_sync(0xffffffffu, p, 2, 16);
        p += __shfl_xor_sync(0xffffffffu, p, 1, 16);
        if (s == 0) yrow[(size_t)t*DINNER] = p;
    }
}

// ---------------- gating: y = (y + xm*D) * silu(z) ----------------
__global__ void gate_kernel(const float* __restrict__ D_param)
{
    int idx = blockIdx.x * blockDim.x + threadIdx.x;
    if (idx >= MTOT * DINNER) return;
    int d  = idx % DINNER;
    int bt = idx / DINNER;
    float z  = g_xz[(size_t)bt*(2*DINNER) + DINNER + d];
    float yv = g_y[idx] + g_xm[idx] * D_param[d];
    g_y[idx] = yv * (z / (1.f + __expf(-z)));
}

// ---------------- host launch ----------------
static float* sym_addr(const void* symbol)
{
    void* p = nullptr;
    cudaGetSymbolAddress(&p, symbol);
    return (float*)p;
}

extern "C" void kernel_launch(void* const* d_in, const int* in_sizes, int n_in,
                              void* d_out, int out_size)
{
    const float* x         = (const float*)d_in[0];
    const float* enc_w1    = (const float*)d_in[1];
    const float* enc_b1    = (const float*)d_in[2];
    const float* enc_w2    = (const float*)d_in[3];
    const float* enc_b2    = (const float*)d_in[4];
    const float* in_proj_w = (const float*)d_in[5];
    const float* conv_w    = (const float*)d_in[6];
    const float* conv_b    = (const float*)d_in[7];
    const float* x_proj_w  = (const float*)d_in[8];
    const float* dt_proj_w = (const float*)d_in[9];
    const float* dt_proj_b = (const float*)d_in[10];
    const float* A_log     = (const float*)d_in[11];
    const float* D_param   = (const float*)d_in[12];
    const float* out_proj_w= (const float*)d_in[13];
    const float* dec_w1    = (const float*)d_in[14];
    const float* dec_b1    = (const float*)d_in[15];
    const float* dec_w2    = (const float*)d_in[16];
    const float* dec_b2    = (const float*)d_in[17];
    float* out = (float*)d_out;

    float* ph    = sym_addr(g_h);
    float* pu    = sym_addr(g_u);
    float* pxz   = sym_addr(g_xz);
    float* pxm   = sym_addr(g_xm);
    float* pdbl  = sym_addr(g_dbl);
    float* pdel  = sym_addr(g_delta);
    float* py    = sym_addr(g_y);
    float* po1   = sym_addr(g_o1);
    float* ph2   = sym_addr(g_h2);

    // dynamic smem sizes: (hi[,lo]) for A (BM rows) + B (BN rows), stride 36 floats
    const int SMEM_PLAIN_BIG   = (128 + 128) * 36 * 4;       // 36864
    const int SMEM_SPLIT_BIG   = 2 * (128 + 128) * 36 * 4;   // 73728
    const int SMEM_SPLIT_NARR  = 2 * (128 + 64) * 36 * 4;    // 55296

    cudaFuncSetAttribute(gemm_tc<128,128,2,4,ACT_RELU,1>,
                         cudaFuncAttributeMaxDynamicSharedMemorySize, SMEM_SPLIT_BIG);
    cudaFuncSetAttribute(gemm_tc<128,128,2,4,ACT_NONE,1>,
                         cudaFuncAttributeMaxDynamicSharedMemorySize, SMEM_SPLIT_BIG);
    cudaFuncSetAttribute(gemm_tc<128,128,2,4,ACT_SOFTPLUS,1>,
                         cudaFuncAttributeMaxDynamicSharedMemorySize, SMEM_SPLIT_BIG);
    cudaFuncSetAttribute(gemm_tc<128,64,4,2,ACT_NONE,1>,
                         cudaFuncAttributeMaxDynamicSharedMemorySize, SMEM_SPLIT_NARR);

    const int EW = MTOT * DINNER;
    const int EW_BLK = 256;
    const int EW_GRID = (EW + EW_BLK - 1) / EW_BLK;

    // 1. encoder layer 1: relu(x @ enc_w1^T + b1)   [16384,256] K=64   (tf32x3)
    gemm_tc<128,128,2,4,ACT_RELU,1><<<dim3(HID/128, MTOT/128), 256, SMEM_SPLIT_BIG>>>(
        x, enc_w1, enc_b1, ph, MTOT, HID, DIN, DIN);

    // 2. encoder layer 2: u = h @ enc_w2^T + b2     [16384,512] K=256  (tf32x3)
    gemm_tc<128,128,2,4,ACT_NONE,1><<<dim3(DMODEL/128, MTOT/128), 256, SMEM_SPLIT_BIG>>>(
        ph, enc_w2, enc_b2, pu, MTOT, DMODEL, HID, HID);

    // 3. in_proj: xz = u @ in_proj_w^T              [16384,2048] K=512 (plain tf32)
    gemm_tc<128,128,2,4,ACT_NONE,0><<<dim3(2*DINNER/128, MTOT/128), 256, SMEM_PLAIN_BIG>>>(
        pu, in_proj_w, nullptr, pxz, MTOT, 2*DINNER, DMODEL, DMODEL);

    // 4. depthwise causal conv + bias + silu -> g_xm
    conv_silu_kernel<<<EW_GRID, EW_BLK>>>(conv_w, conv_b);

    // 5. x_proj: dbl = xm @ x_proj_w^T              [16384,64] K=1024  (tf32x3)
    gemm_tc<128,64,4,2,ACT_NONE,1><<<dim3(64/64, MTOT/128), 256, SMEM_SPLIT_NARR>>>(
        pxm, x_proj_w, nullptr, pdbl, MTOT, 64, DINNER, DINNER);

    // 6. dt_proj + softplus: delta                  [16384,1024] K=32, lda=64 (tf32x3)
    gemm_tc<128,128,2,4,ACT_SOFTPLUS,1><<<dim3(DINNER/128, MTOT/128), 256, SMEM_SPLIT_BIG>>>(
        pdbl, dt_proj_w, dt_proj_b, pdel, MTOT, DINNER, DTRANK, 64);

    // 7. selective scan -> g_y
    scan_kernel<<<(BATCH*DINNER*DSTATE)/256, 256>>>(A_log);

    // 8. gating: y = (y + xm*D) * silu(z)
    gate_kernel<<<EW_GRID, EW_BLK>>>(D_param);

    // 9. out_proj: o1 = y @ out_proj_w^T            [16384,512] K=1024 (plain tf32)
    gemm_tc<128,128,2,4,ACT_NONE,0><<<dim3(DMODEL/128, MTOT/128), 256, SMEM_PLAIN_BIG>>>(
        py, out_proj_w, nullptr, po1, MTOT, DMODEL, DINNER, DINNER);

    // 10. decoder layer 1: relu                     [16384,256] K=512  (tf32x3)
    gemm_tc<128,128,2,4,ACT_RELU,1><<<dim3(HID/128, MTOT/128), 256, SMEM_SPLIT_BIG>>>(
        po1, dec_w1, dec_b1, ph2, MTOT, HID, DMODEL, DMODEL);

    // 11. decoder layer 2 -> out                    [16384,64] K=256   (tf32x3)
    gemm_tc<128,64,4,2,ACT_NONE,1><<<dim3(DOUTD/64, MTOT/128), 256, SMEM_SPLIT_NARR>>>(
        ph2, dec_w2, dec_b2, out, MTOT, DOUTD, HID, HID);
}